// round 1
// baseline (speedup 1.0000x reference)
#include <cuda_runtime.h>
#include <math.h>

#define B_ 2
#define S_ 2048
#define DM_ 2048
#define H_ 8
#define DH_ 128
#define INNER_ 1024
#define MROWS (B_*S_)   // 4096

// ---------------- scratch (device globals; no allocation allowed) ----------
__device__ float g_q[MROWS * INNER_];
__device__ float g_k[MROWS * INNER_];
__device__ float g_v[MROWS * INNER_];
__device__ float g_attn[MROWS * INNER_];
__device__ float g_beta[MROWS * H_];
__device__ float g_amean[H_];

__device__ __forceinline__ float sigmoidf_(float x) {
    return 1.0f / (1.0f + expf(-x));
}

// ---------------- alpha_mean per head ----------------
__global__ void amean_kernel(const float* __restrict__ alpha_log) {
    int w = threadIdx.x >> 5;   // head (8 warps)
    int lane = threadIdx.x & 31;
    float s = 0.f;
    for (int d = lane; d < DH_; d += 32)
        s += sigmoidf_(alpha_log[w * DH_ + d]);
    #pragma unroll
    for (int o = 16; o; o >>= 1) s += __shfl_xor_sync(0xffffffffu, s, o);
    if (lane == 0) g_amean[w] = s / (float)DH_;
}

// ---------------- beta = sigmoid(x @ Wb^T + bb) ----------------
__global__ __launch_bounds__(256) void beta_kernel(const float* __restrict__ x,
                                                   const float* __restrict__ Wb,
                                                   const float* __restrict__ bb,
                                                   float* __restrict__ beta) {
    __shared__ float xs[DM_];
    int row = blockIdx.x;            // b*S + s
    for (int i = threadIdx.x; i < DM_; i += 256)
        xs[i] = x[row * DM_ + i];
    __syncthreads();
    int w = threadIdx.x >> 5;        // head
    int lane = threadIdx.x & 31;
    const float* wr = Wb + w * DM_;
    float sum = 0.f;
    for (int i = lane; i < DM_; i += 32)
        sum += xs[i] * wr[i];
    #pragma unroll
    for (int o = 16; o; o >>= 1) sum += __shfl_xor_sync(0xffffffffu, sum, o);
    if (lane == 0) beta[row * H_ + w] = sigmoidf_(sum + bb[w]);
}

// ---------------- SGEMM (NT): C[M,N] = A[M,K] * W[N,K]^T ----------------
// BM=BN=128, BK=8, 256 threads, 8x8 per thread.
__global__ __launch_bounds__(256) void sgemm_nt(const float* __restrict__ A,
                                                const float* __restrict__ W,
                                                float* __restrict__ C,
                                                int M, int N, int K) {
    __shared__ float As[8][128];
    __shared__ float Ws[8][128];
    int tid = threadIdx.x;
    int m0 = blockIdx.y * 128;
    int n0 = blockIdx.x * 128;
    int lr = tid >> 1;            // 0..127
    int lc = (tid & 1) * 4;       // 0 or 4
    int ty = tid >> 4;            // 0..15 -> rows
    int tx = tid & 15;            // 0..15 -> cols

    float acc[8][8];
    #pragma unroll
    for (int i = 0; i < 8; i++)
        #pragma unroll
        for (int j = 0; j < 8; j++) acc[i][j] = 0.f;

    const float* Ap = A + (size_t)(m0 + lr) * K + lc;
    const float* Wp = W + (size_t)(n0 + lr) * K + lc;

    for (int k0 = 0; k0 < K; k0 += 8) {
        float4 a4 = *(const float4*)(Ap + k0);
        float4 w4 = *(const float4*)(Wp + k0);
        As[lc + 0][lr] = a4.x; As[lc + 1][lr] = a4.y;
        As[lc + 2][lr] = a4.z; As[lc + 3][lr] = a4.w;
        Ws[lc + 0][lr] = w4.x; Ws[lc + 1][lr] = w4.y;
        Ws[lc + 2][lr] = w4.z; Ws[lc + 3][lr] = w4.w;
        __syncthreads();
        #pragma unroll
        for (int kk = 0; kk < 8; kk++) {
            float ra[8], rb[8];
            float4 t0 = *(const float4*)&As[kk][ty * 8];
            float4 t1 = *(const float4*)&As[kk][ty * 8 + 4];
            ra[0] = t0.x; ra[1] = t0.y; ra[2] = t0.z; ra[3] = t0.w;
            ra[4] = t1.x; ra[5] = t1.y; ra[6] = t1.z; ra[7] = t1.w;
            float4 u0 = *(const float4*)&Ws[kk][tx * 8];
            float4 u1 = *(const float4*)&Ws[kk][tx * 8 + 4];
            rb[0] = u0.x; rb[1] = u0.y; rb[2] = u0.z; rb[3] = u0.w;
            rb[4] = u1.x; rb[5] = u1.y; rb[6] = u1.z; rb[7] = u1.w;
            #pragma unroll
            for (int i = 0; i < 8; i++)
                #pragma unroll
                for (int j = 0; j < 8; j++)
                    acc[i][j] = fmaf(ra[i], rb[j], acc[i][j]);
        }
        __syncthreads();
    }
    #pragma unroll
    for (int i = 0; i < 8; i++) {
        float4 o0 = make_float4(acc[i][0], acc[i][1], acc[i][2], acc[i][3]);
        float4 o1 = make_float4(acc[i][4], acc[i][5], acc[i][6], acc[i][7]);
        float* cp = C + (size_t)(m0 + ty * 8 + i) * N + n0 + tx * 8;
        *(float4*)(cp) = o0;
        *(float4*)(cp + 4) = o1;
    }
}

// ---------------- RoPE in-place on q and k ----------------
__global__ void rope_kernel(float* __restrict__ q, float* __restrict__ k) {
    int idx = blockIdx.x * blockDim.x + threadIdx.x;   // < B*S*H*64
    int j = idx & 63;
    int h = (idx >> 6) & (H_ - 1);
    int row = idx >> 9;                 // b*S + s  (< 4096)
    int s = row & (S_ - 1);
    float ex = (float)(2 * j) * (1.0f / (float)DH_);
    float inv = powf(10000.0f, -ex);
    float ang = (float)s * inv;
    float sn, c;
    sincosf(ang, &sn, &c);
    int base = row * INNER_ + h * DH_ + j;
    float x1 = q[base], x2 = q[base + 64];
    q[base]      = x1 * c - x2 * sn;
    q[base + 64] = x2 * c + x1 * sn;
    x1 = k[base]; x2 = k[base + 64];
    k[base]      = x1 * c - x2 * sn;
    k[base + 64] = x2 * c + x1 * sn;
}

// ---------------- windowed decay attention ----------------
// out[b,s,h,:] = sum_{t=s-31..s} (q_s . k_t) * amean^(s-t) * beta[b,t,h] * v_t
#define WIN_ 32
__global__ __launch_bounds__(256) void attn_kernel(const float* __restrict__ q,
                                                   const float* __restrict__ k,
                                                   const float* __restrict__ v,
                                                   const float* __restrict__ beta,
                                                   float* __restrict__ attn) {
    int gw = (blockIdx.x * 256 + threadIdx.x) >> 5;   // global warp id
    int lane = threadIdx.x & 31;
    int s = gw & (S_ - 1);
    int h = (gw >> 11) & (H_ - 1);
    int b = gw >> 14;
    float am = g_amean[h];
    size_t colbase = (size_t)b * S_ * INNER_ + h * DH_ + lane * 4;
    float4 qv = *(const float4*)(q + colbase + (size_t)s * INNER_);
    float4 acc = make_float4(0.f, 0.f, 0.f, 0.f);
    float decay = 1.f;
    int t_lo = s - (WIN_ - 1); if (t_lo < 0) t_lo = 0;
    for (int t = s; t >= t_lo; t--) {
        float4 kv = *(const float4*)(k + colbase + (size_t)t * INNER_);
        float d = qv.x * kv.x + qv.y * kv.y + qv.z * kv.z + qv.w * kv.w;
        #pragma unroll
        for (int o = 16; o; o >>= 1) d += __shfl_xor_sync(0xffffffffu, d, o);
        float w = d * decay * beta[(b * S_ + t) * H_ + h];
        float4 vv = *(const float4*)(v + colbase + (size_t)t * INNER_);
        acc.x = fmaf(w, vv.x, acc.x);
        acc.y = fmaf(w, vv.y, acc.y);
        acc.z = fmaf(w, vv.z, acc.z);
        acc.w = fmaf(w, vv.w, acc.w);
        decay *= am;
    }
    *(float4*)(attn + colbase + (size_t)s * INNER_) = acc;
}

// ---------------- final recurrent state (windowed scan) ----------------
// state[b,h,d,e] = sum_t alpha[h,d]^(S-1-t) * beta[b,t,h] * k[b,t,h,d] * v[b,t,h,e]
#define STWIN_ 128
__global__ __launch_bounds__(256) void state_kernel(const float* __restrict__ k,
                                                    const float* __restrict__ v,
                                                    const float* __restrict__ beta,
                                                    const float* __restrict__ alpha_log,
                                                    float* __restrict__ stout) {
    int b = blockIdx.x >> 3;
    int h = blockIdx.x & 7;
    int tid = threadIdx.x;
    int d = tid >> 1;
    int e0 = (tid & 1) * 64;
    __shared__ float ks[DH_], vs[DH_];
    float st[64];
    #pragma unroll
    for (int e = 0; e < 64; e++) st[e] = 0.f;
    float ad = sigmoidf_(alpha_log[h * DH_ + d]);
    for (int t = S_ - STWIN_; t < S_; t++) {
        __syncthreads();
        size_t base = (size_t)(b * S_ + t) * INNER_ + h * DH_;
        if (tid < 128) ks[tid] = k[base + tid];
        else           vs[tid - 128] = v[base + tid - 128];
        __syncthreads();
        float kb = ks[d] * beta[(b * S_ + t) * H_ + h];
        #pragma unroll
        for (int e = 0; e < 64; e++)
            st[e] = fmaf(ad, st[e], kb * vs[e0 + e]);
    }
    float* op = stout + ((size_t)(b * H_ + h) * DH_ + d) * DH_ + e0;
    #pragma unroll
    for (int e = 0; e < 64; e++) op[e] = st[e];
}

// ---------------- launch ----------------
extern "C" void kernel_launch(void* const* d_in, const int* in_sizes, int n_in,
                              void* d_out, int out_size) {
    const float* x         = (const float*)d_in[0];
    const float* Wq        = (const float*)d_in[1];
    const float* Wk        = (const float*)d_in[2];
    const float* Wv        = (const float*)d_in[3];
    const float* Wo        = (const float*)d_in[4];
    const float* Wb        = (const float*)d_in[5];
    const float* bb        = (const float*)d_in[6];
    const float* alpha_log = (const float*)d_in[7];
    float* out = (float*)d_out;

    float *q, *k, *v, *attn, *beta;
    cudaGetSymbolAddress((void**)&q,    g_q);
    cudaGetSymbolAddress((void**)&k,    g_k);
    cudaGetSymbolAddress((void**)&v,    g_v);
    cudaGetSymbolAddress((void**)&attn, g_attn);
    cudaGetSymbolAddress((void**)&beta, g_beta);

    amean_kernel<<<1, 256>>>(alpha_log);
    beta_kernel<<<MROWS, 256>>>(x, Wb, bb, beta);

    dim3 gqkv(INNER_ / 128, MROWS / 128);
    sgemm_nt<<<gqkv, 256>>>(x, Wq, q, MROWS, INNER_, DM_);
    sgemm_nt<<<gqkv, 256>>>(x, Wk, k, MROWS, INNER_, DM_);
    sgemm_nt<<<gqkv, 256>>>(x, Wv, v, MROWS, INNER_, DM_);

    rope_kernel<<<(B_ * S_ * H_ * 64) / 256, 256>>>(q, k);

    attn_kernel<<<(B_ * H_ * S_) / 8, 256>>>(q, k, v, beta, attn);

    dim3 gout(DM_ / 128, MROWS / 128);
    sgemm_nt<<<gout, 256>>>(attn, Wo, out, MROWS, DM_, INNER_);

    state_kernel<<<B_ * H_, 256>>>(k, v, beta, alpha_log, out + (size_t)MROWS * DM_);
}

// round 3
// speedup vs baseline: 2.5717x; 2.5717x over previous
#include <cuda_runtime.h>
#include <cuda_bf16.h>
#include <math.h>
#include <stdint.h>

#define B_ 2
#define S_ 2048
#define DM_ 2048
#define H_ 8
#define DH_ 128
#define INNER_ 1024
#define MROWS (B_*S_)   // 4096

// ---------------- scratch (device globals; no allocation allowed) ----------
__device__ float g_q[MROWS * INNER_];
__device__ float g_k[MROWS * INNER_];
__device__ float g_v[MROWS * INNER_];
__device__ float g_attn[MROWS * INNER_];
__device__ float g_beta[MROWS * H_];
__device__ float g_amean[H_];

__device__ __nv_bfloat16 g_xhi[MROWS * DM_];
__device__ __nv_bfloat16 g_xlo[MROWS * DM_];
__device__ __nv_bfloat16 g_wqhi[INNER_ * DM_];
__device__ __nv_bfloat16 g_wqlo[INNER_ * DM_];
__device__ __nv_bfloat16 g_wkhi[INNER_ * DM_];
__device__ __nv_bfloat16 g_wklo[INNER_ * DM_];
__device__ __nv_bfloat16 g_wvhi[INNER_ * DM_];
__device__ __nv_bfloat16 g_wvlo[INNER_ * DM_];
__device__ __nv_bfloat16 g_wohi[DM_ * INNER_];
__device__ __nv_bfloat16 g_wolo[DM_ * INNER_];
__device__ __nv_bfloat16 g_ahi[MROWS * INNER_];
__device__ __nv_bfloat16 g_alo[MROWS * INNER_];

__device__ __forceinline__ float sigmoidf_(float x) {
    return 1.0f / (1.0f + expf(-x));
}

// ======================= PTX helpers ==============================
__device__ __forceinline__ uint32_t smem_u32(const void* p) {
    uint32_t a;
    asm("{ .reg .u64 t; cvta.to.shared.u64 t, %1; cvt.u32.u64 %0, t; }"
        : "=r"(a) : "l"(p));
    return a;
}

#define CP_ASYNC16(dst, src) \
    asm volatile("cp.async.cg.shared.global [%0], [%1], 16;" :: "r"(dst), "l"(src) : "memory")
#define CP_COMMIT() asm volatile("cp.async.commit_group;" ::: "memory")
#define CP_WAIT(n)  asm volatile("cp.async.wait_group %0;" :: "n"(n) : "memory")

__device__ __forceinline__ void ldsm_x4(uint32_t& r0, uint32_t& r1, uint32_t& r2, uint32_t& r3,
                                        uint32_t addr) {
    asm volatile("ldmatrix.sync.aligned.m8n8.x4.shared.b16 {%0,%1,%2,%3}, [%4];"
        : "=r"(r0), "=r"(r1), "=r"(r2), "=r"(r3) : "r"(addr));
}

__device__ __forceinline__ void mma16816(float* c, const uint32_t* a, uint32_t b0, uint32_t b1) {
    asm volatile(
        "mma.sync.aligned.m16n8k16.row.col.f32.bf16.bf16.f32 "
        "{%0,%1,%2,%3}, {%4,%5,%6,%7}, {%8,%9}, {%0,%1,%2,%3};"
        : "+f"(c[0]), "+f"(c[1]), "+f"(c[2]), "+f"(c[3])
        : "r"(a[0]), "r"(a[1]), "r"(a[2]), "r"(a[3]), "r"(b0), "r"(b1));
}

// ======================= fp32 -> bf16 hi/lo split ==========================
__global__ void split_kernel(const float* __restrict__ src,
                             __nv_bfloat16* __restrict__ hi,
                             __nv_bfloat16* __restrict__ lo, int n4) {
    int i = blockIdx.x * blockDim.x + threadIdx.x;
    if (i >= n4) return;
    float4 v = ((const float4*)src)[i];
    __nv_bfloat16 h0 = __float2bfloat16(v.x);
    __nv_bfloat16 h1 = __float2bfloat16(v.y);
    __nv_bfloat16 h2 = __float2bfloat16(v.z);
    __nv_bfloat16 h3 = __float2bfloat16(v.w);
    __nv_bfloat16 l0 = __float2bfloat16(v.x - __bfloat162float(h0));
    __nv_bfloat16 l1 = __float2bfloat16(v.y - __bfloat162float(h1));
    __nv_bfloat16 l2 = __float2bfloat16(v.z - __bfloat162float(h2));
    __nv_bfloat16 l3 = __float2bfloat16(v.w - __bfloat162float(h3));
    __nv_bfloat162* hp = (__nv_bfloat162*)hi;
    __nv_bfloat162* lp = (__nv_bfloat162*)lo;
    hp[2*i]   = __nv_bfloat162(h0, h1);
    hp[2*i+1] = __nv_bfloat162(h2, h3);
    lp[2*i]   = __nv_bfloat162(l0, l1);
    lp[2*i+1] = __nv_bfloat162(l2, l3);
}

// ======================= HMMA split-3 GEMM ===============================
// C[M,N](fp32) = (Ah+Al)[M,K] @ (Bh+Bl)[N,K]^T, dropping Al*Bl.
// 128x128x64 tile, 3-stage cp.async, xor-swizzled SMEM, mma.m16n8k16.
#define NSTG 3
#define STG_BYTES 32768              // A 16KB + B 16KB
#define GEMM_SMEM (NSTG * STG_BYTES) // 96KB

__global__ __launch_bounds__(256, 2) void hmma_gemm(
    const __nv_bfloat16* __restrict__ Ah, const __nv_bfloat16* __restrict__ Al,
    const __nv_bfloat16* __restrict__ B0h, const __nv_bfloat16* __restrict__ B0l,
    const __nv_bfloat16* __restrict__ B1h, const __nv_bfloat16* __restrict__ B1l,
    const __nv_bfloat16* __restrict__ B2h, const __nv_bfloat16* __restrict__ B2l,
    float* __restrict__ C0, float* __restrict__ C1, float* __restrict__ C2,
    int K, int ldc, int klog) {
    extern __shared__ char smem[];
    uint32_t sm = smem_u32(smem);
    int tid = threadIdx.x;
    int lane = tid & 31;
    int wid = tid >> 5;
    int wm = wid & 1;          // 2 M-blocks of 64
    int wn = wid >> 1;         // 4 N-blocks of 32
    int m0 = blockIdx.y * 128;
    int n0 = blockIdx.x * 128;

    const __nv_bfloat16 *Bh, *Bl;
    float* C;
    if (blockIdx.z == 0)      { Bh = B0h; Bl = B0l; C = C0; }
    else if (blockIdx.z == 1) { Bh = B1h; Bl = B1l; C = C1; }
    else                      { Bh = B2h; Bl = B2l; C = C2; }

    const __nv_bfloat16* Ap[3] = {Ah, Ah, Al};
    const __nv_bfloat16* Bp[3] = {Bh, Bl, Bh};
    int kiters = K >> 6;
    int niter = 3 * kiters;
    int kmask = kiters - 1;

    float acc[4][4][4];
    #pragma unroll
    for (int i = 0; i < 4; i++)
        #pragma unroll
        for (int j = 0; j < 4; j++)
            #pragma unroll
            for (int t = 0; t < 4; t++) acc[i][j][t] = 0.f;

    int lc = tid & 7;          // 16B chunk col
    int lr = tid >> 3;         // 0..31

    // -------- loader (all 256 threads) --------
    #define ISSUE_STAGE(ip, buf) do {                                          \
        int _pass = (ip) >> klog;                                              \
        int _k0 = ((ip) & kmask) << 6;                                         \
        const __nv_bfloat16* _Ab = Ap[_pass] + (size_t)(m0 + lr) * K + _k0 + lc * 8; \
        const __nv_bfloat16* _Bb = Bp[_pass] + (size_t)(n0 + lr) * K + _k0 + lc * 8; \
        uint32_t _sb = sm + (buf) * STG_BYTES;                                 \
        _Pragma("unroll")                                                      \
        for (int _i = 0; _i < 4; _i++) {                                       \
            int _row = lr + 32 * _i;                                           \
            uint32_t _sw = ((uint32_t)_row << 7) + (((uint32_t)(lc ^ (_row & 7))) << 4); \
            CP_ASYNC16(_sb + _sw, _Ab + (size_t)(32 * _i) * K);                \
            CP_ASYNC16(_sb + 16384u + _sw, _Bb + (size_t)(32 * _i) * K);       \
        }                                                                      \
    } while (0)

    ISSUE_STAGE(0, 0); CP_COMMIT();
    ISSUE_STAGE(1, 1); CP_COMMIT();

    int buf = 0;       // compute buffer
    int ibuf = 2;      // issue buffer
    for (int it = 0; it < niter; ++it) {
        if (it + 2 < niter) ISSUE_STAGE(it + 2, ibuf);
        CP_COMMIT();
        CP_WAIT(2);
        __syncthreads();

        uint32_t sa = sm + buf * STG_BYTES;
        uint32_t sb = sa + 16384u;
        #pragma unroll
        for (int ks = 0; ks < 4; ++ks) {
            uint32_t a[4][4];
            int ch = ks * 2 + (lane >> 4);
            #pragma unroll
            for (int mt = 0; mt < 4; ++mt) {
                int rowA = wm * 64 + mt * 16 + (lane & 7) + ((lane >> 3) & 1) * 8;
                uint32_t ad = sa + ((uint32_t)rowA << 7) + (((uint32_t)(ch ^ (rowA & 7))) << 4);
                ldsm_x4(a[mt][0], a[mt][1], a[mt][2], a[mt][3], ad);
            }
            #pragma unroll
            for (int nt2 = 0; nt2 < 2; ++nt2) {
                int rowB = wn * 32 + nt2 * 16 + (lane & 7) + ((lane >> 3) & 1) * 8;
                uint32_t bd = sb + ((uint32_t)rowB << 7) + (((uint32_t)(ch ^ (rowB & 7))) << 4);
                uint32_t r0, r1, r2, r3;
                ldsm_x4(r0, r1, r2, r3, bd);
                #pragma unroll
                for (int mt = 0; mt < 4; ++mt) {
                    mma16816(acc[mt][nt2 * 2 + 0], a[mt], r0, r2);
                    mma16816(acc[mt][nt2 * 2 + 1], a[mt], r1, r3);
                }
            }
        }
        __syncthreads();
        buf = (buf == 2) ? 0 : buf + 1;
        ibuf = (ibuf == 2) ? 0 : ibuf + 1;
    }

    // -------- epilogue --------
    #pragma unroll
    for (int mt = 0; mt < 4; ++mt) {
        int m = m0 + wm * 64 + mt * 16 + (lane >> 2);
        #pragma unroll
        for (int nt = 0; nt < 4; ++nt) {
            int n = n0 + wn * 32 + nt * 8 + (lane & 3) * 2;
            float* p = C + (size_t)m * ldc + n;
            *(float2*)p = make_float2(acc[mt][nt][0], acc[mt][nt][1]);
            *(float2*)(p + 8 * (size_t)ldc) = make_float2(acc[mt][nt][2], acc[mt][nt][3]);
        }
    }
}

// ---------------- alpha_mean per head ----------------
__global__ void amean_kernel(const float* __restrict__ alpha_log) {
    int w = threadIdx.x >> 5;
    int lane = threadIdx.x & 31;
    float s = 0.f;
    for (int d = lane; d < DH_; d += 32)
        s += sigmoidf_(alpha_log[w * DH_ + d]);
    #pragma unroll
    for (int o = 16; o; o >>= 1) s += __shfl_xor_sync(0xffffffffu, s, o);
    if (lane == 0) g_amean[w] = s / (float)DH_;
}

// ---------------- beta = sigmoid(x @ Wb^T + bb) ----------------
__global__ __launch_bounds__(256) void beta_kernel(const float* __restrict__ x,
                                                   const float* __restrict__ Wb,
                                                   const float* __restrict__ bb,
                                                   float* __restrict__ beta) {
    __shared__ float xs[DM_];
    int row = blockIdx.x;
    for (int i = threadIdx.x; i < DM_; i += 256)
        xs[i] = x[row * DM_ + i];
    __syncthreads();
    int w = threadIdx.x >> 5;
    int lane = threadIdx.x & 31;
    const float* wr = Wb + w * DM_;
    float sum = 0.f;
    for (int i = lane; i < DM_; i += 32)
        sum += xs[i] * wr[i];
    #pragma unroll
    for (int o = 16; o; o >>= 1) sum += __shfl_xor_sync(0xffffffffu, sum, o);
    if (lane == 0) beta[row * H_ + w] = sigmoidf_(sum + bb[w]);
}

// ---------------- RoPE in-place on q and k ----------------
__global__ void rope_kernel(float* __restrict__ q, float* __restrict__ k) {
    int idx = blockIdx.x * blockDim.x + threadIdx.x;
    int j = idx & 63;
    int h = (idx >> 6) & (H_ - 1);
    int row = idx >> 9;
    int s = row & (S_ - 1);
    float ex = (float)(2 * j) * (1.0f / (float)DH_);
    float inv = powf(10000.0f, -ex);
    float ang = (float)s * inv;
    float sn, c;
    sincosf(ang, &sn, &c);
    int base = row * INNER_ + h * DH_ + j;
    float x1 = q[base], x2 = q[base + 64];
    q[base]      = x1 * c - x2 * sn;
    q[base + 64] = x2 * c + x1 * sn;
    x1 = k[base]; x2 = k[base + 64];
    k[base]      = x1 * c - x2 * sn;
    k[base + 64] = x2 * c + x1 * sn;
}

// ---------------- windowed decay attention ----------------
#define WIN_ 32
__global__ __launch_bounds__(256) void attn_kernel(const float* __restrict__ q,
                                                   const float* __restrict__ k,
                                                   const float* __restrict__ v,
                                                   const float* __restrict__ beta,
                                                   float* __restrict__ attn) {
    int gw = (blockIdx.x * 256 + threadIdx.x) >> 5;
    int lane = threadIdx.x & 31;
    int s = gw & (S_ - 1);
    int h = (gw >> 11) & (H_ - 1);
    int b = gw >> 14;
    float am = g_amean[h];
    size_t colbase = (size_t)b * S_ * INNER_ + h * DH_ + lane * 4;
    float4 qv = *(const float4*)(q + colbase + (size_t)s * INNER_);
    float4 acc = make_float4(0.f, 0.f, 0.f, 0.f);
    float decay = 1.f;
    int t_lo = s - (WIN_ - 1); if (t_lo < 0) t_lo = 0;
    for (int t = s; t >= t_lo; t--) {
        float4 kv = *(const float4*)(k + colbase + (size_t)t * INNER_);
        float d = qv.x * kv.x + qv.y * kv.y + qv.z * kv.z + qv.w * kv.w;
        #pragma unroll
        for (int o = 16; o; o >>= 1) d += __shfl_xor_sync(0xffffffffu, d, o);
        float w = d * decay * beta[(b * S_ + t) * H_ + h];
        float4 vv = *(const float4*)(v + colbase + (size_t)t * INNER_);
        acc.x = fmaf(w, vv.x, acc.x);
        acc.y = fmaf(w, vv.y, acc.y);
        acc.z = fmaf(w, vv.z, acc.z);
        acc.w = fmaf(w, vv.w, acc.w);
        decay *= am;
    }
    *(float4*)(attn + colbase + (size_t)s * INNER_) = acc;
}

// ---------------- final recurrent state (windowed scan) ----------------
#define STWIN_ 128
__global__ __launch_bounds__(256) void state_kernel(const float* __restrict__ k,
                                                    const float* __restrict__ v,
                                                    const float* __restrict__ beta,
                                                    const float* __restrict__ alpha_log,
                                                    float* __restrict__ stout) {
    int b = blockIdx.x >> 3;
    int h = blockIdx.x & 7;
    int tid = threadIdx.x;
    int d = tid >> 1;
    int e0 = (tid & 1) * 64;
    __shared__ float ks[DH_], vs[DH_];
    float st[64];
    #pragma unroll
    for (int e = 0; e < 64; e++) st[e] = 0.f;
    float ad = sigmoidf_(alpha_log[h * DH_ + d]);
    for (int t = S_ - STWIN_; t < S_; t++) {
        __syncthreads();
        size_t base = (size_t)(b * S_ + t) * INNER_ + h * DH_;
        if (tid < 128) ks[tid] = k[base + tid];
        else           vs[tid - 128] = v[base + tid - 128];
        __syncthreads();
        float kb = ks[d] * beta[(b * S_ + t) * H_ + h];
        #pragma unroll
        for (int e = 0; e < 64; e++)
            st[e] = fmaf(ad, st[e], kb * vs[e0 + e]);
    }
    float* op = stout + ((size_t)(b * H_ + h) * DH_ + d) * DH_ + e0;
    #pragma unroll
    for (int e = 0; e < 64; e++) op[e] = st[e];
}

// ---------------- launch ----------------
extern "C" void kernel_launch(void* const* d_in, const int* in_sizes, int n_in,
                              void* d_out, int out_size) {
    const float* x         = (const float*)d_in[0];
    const float* Wq        = (const float*)d_in[1];
    const float* Wk        = (const float*)d_in[2];
    const float* Wv        = (const float*)d_in[3];
    const float* Wo        = (const float*)d_in[4];
    const float* Wb        = (const float*)d_in[5];
    const float* bb        = (const float*)d_in[6];
    const float* alpha_log = (const float*)d_in[7];
    float* out = (float*)d_out;

    float *q, *k, *v, *attn, *beta;
    cudaGetSymbolAddress((void**)&q,    g_q);
    cudaGetSymbolAddress((void**)&k,    g_k);
    cudaGetSymbolAddress((void**)&v,    g_v);
    cudaGetSymbolAddress((void**)&attn, g_attn);
    cudaGetSymbolAddress((void**)&beta, g_beta);
    __nv_bfloat16 *xhi, *xlo, *wqhi, *wqlo, *wkhi, *wklo, *wvhi, *wvlo, *wohi, *wolo, *ahi, *alo;
    cudaGetSymbolAddress((void**)&xhi,  g_xhi);
    cudaGetSymbolAddress((void**)&xlo,  g_xlo);
    cudaGetSymbolAddress((void**)&wqhi, g_wqhi);
    cudaGetSymbolAddress((void**)&wqlo, g_wqlo);
    cudaGetSymbolAddress((void**)&wkhi, g_wkhi);
    cudaGetSymbolAddress((void**)&wklo, g_wklo);
    cudaGetSymbolAddress((void**)&wvhi, g_wvhi);
    cudaGetSymbolAddress((void**)&wvlo, g_wvlo);
    cudaGetSymbolAddress((void**)&wohi, g_wohi);
    cudaGetSymbolAddress((void**)&wolo, g_wolo);
    cudaGetSymbolAddress((void**)&ahi,  g_ahi);
    cudaGetSymbolAddress((void**)&alo,  g_alo);

    cudaFuncSetAttribute(hmma_gemm, cudaFuncAttributeMaxDynamicSharedMemorySize, GEMM_SMEM);

    amean_kernel<<<1, 256>>>(alpha_log);
    beta_kernel<<<MROWS, 256>>>(x, Wb, bb, beta);

    // fp32 -> bf16 hi/lo splits
    split_kernel<<<(MROWS*DM_/4 + 255)/256, 256>>>(x, xhi, xlo, MROWS*DM_/4);
    split_kernel<<<(INNER_*DM_/4 + 255)/256, 256>>>(Wq, wqhi, wqlo, INNER_*DM_/4);
    split_kernel<<<(INNER_*DM_/4 + 255)/256, 256>>>(Wk, wkhi, wklo, INNER_*DM_/4);
    split_kernel<<<(INNER_*DM_/4 + 255)/256, 256>>>(Wv, wvhi, wvlo, INNER_*DM_/4);
    split_kernel<<<(DM_*INNER_/4 + 255)/256, 256>>>(Wo, wohi, wolo, DM_*INNER_/4);

    // QKV: fused 3-way GEMM, M=4096, N=1024, K=2048 (kiters=32, klog=5)
    dim3 gqkv(INNER_/128, MROWS/128, 3);
    hmma_gemm<<<gqkv, 256, GEMM_SMEM>>>(xhi, xlo,
                                        wqhi, wqlo, wkhi, wklo, wvhi, wvlo,
                                        q, k, v, DM_, INNER_, 5);

    rope_kernel<<<(B_ * S_ * H_ * 64) / 256, 256>>>(q, k);
    attn_kernel<<<(B_ * H_ * S_) / 8, 256>>>(q, k, v, beta, attn);

    split_kernel<<<(MROWS*INNER_/4 + 255)/256, 256>>>(attn, ahi, alo, MROWS*INNER_/4);

    // O-proj: M=4096, N=2048, K=1024 (kiters=16, klog=4)
    dim3 gout(DM_/128, MROWS/128, 1);
    hmma_gemm<<<gout, 256, GEMM_SMEM>>>(ahi, alo,
                                        wohi, wolo, wohi, wolo, wohi, wolo,
                                        out, out, out, INNER_, DM_, 4);

    state_kernel<<<B_ * H_, 256>>>(k, v, beta, alpha_log, out + (size_t)MROWS * DM_);
}